// round 2
// baseline (speedup 1.0000x reference)
#include <cuda_runtime.h>

#define AZI_C 0.006135923151542565f
#define INC_C 0.008267349088394194f

#define NPIX 262144          // total pixels (B*W*H)
#define PPB  65536           // pixels per batch (W*H)

// scratch (alloc-free rule: device globals)
__device__ float g_U[64 * NPIX];     // 64 MB
__device__ float g_V[64 * NPIX];     // 64 MB
__device__ float g_mean[128];
__device__ float g_rstd[128];

// ---------------------------------------------------------------------------
// GroupNorm statistics: one block per (batch, group). Each group's data is
// 131072 contiguous floats (2 channels x 65536 pixels, channels contiguous).
// ---------------------------------------------------------------------------
__global__ void gn_stats_kernel(const float* __restrict__ in) {
    int bg = blockIdx.x;                  // b*32 + g
    int t  = threadIdx.x;
    const float4* base = reinterpret_cast<const float4*>(in + (size_t)bg * 131072);
    float s = 0.f, q = 0.f;
    for (int i = t; i < 32768; i += 256) {
        float4 v = base[i];
        s += (v.x + v.y) + (v.z + v.w);
        q += (v.x * v.x + v.y * v.y) + (v.z * v.z + v.w * v.w);
    }
    __shared__ float rs[256];
    __shared__ float rq[256];
    rs[t] = s; rq[t] = q;
    __syncthreads();
    for (int off = 128; off > 0; off >>= 1) {
        if (t < off) { rs[t] += rs[t + off]; rq[t] += rq[t + off]; }
        __syncthreads();
    }
    if (t == 0) {
        float mean = rs[0] * (1.f / 131072.f);
        float var  = rq[0] * (1.f / 131072.f) - mean * mean;
        g_mean[bg] = mean;
        g_rstd[bg] = rsqrtf(var + 1e-6f);
    }
}

// ---------------------------------------------------------------------------
// Dual GEMM: [Wa; Wb] (128x64) @ gn1 (64x128pix tile) with groupnorm+relu
// fused into the A(tile)-load and the V' epilogue (+b1 - r*w_p0).
// Grid: 2048 CTAs x 256 threads. Thread tile: 8 outputs x 8 pixels.
// ---------------------------------------------------------------------------
__global__ __launch_bounds__(256) void gemm_uv_kernel(
    const float* __restrict__ xin, const float* __restrict__ r,
    const float* __restrict__ w1, const float* __restrict__ b1,
    const float* __restrict__ gnw, const float* __restrict__ gnb)
{
    extern __shared__ float sm[];
    float* sW = sm;            // [64][128] k-major: sW[k*128+m]
    float* sX = sm + 8192;     // [64][128] gn1 tile: sX[k*128+j]
    float* sR = sm + 16384;    // [128] center r

    int t  = threadIdx.x;
    int p0 = blockIdx.x << 7;         // global pixel base (tile of 128)
    int b  = p0 >> 16;
    int pl = p0 & 65535;
    int bgBase = b << 5;

    // weights: m<64 -> Wa row m (cols 0..63 of w1), m>=64 -> Wb row m-64 (cols 64..127)
    for (int e = t; e < 8192; e += 256) {
        int k = e >> 7, m = e & 127;
        float v = (m < 64) ? w1[m * 131 + k] : w1[(m - 64) * 131 + 64 + k];
        sW[k * 128 + m] = v;
    }
    // input tile with fused groupnorm + relu
    for (int e = t; e < 8192; e += 256) {
        int k = e >> 7, j = e & 127;
        int grp = bgBase + (k >> 1);
        float sc = g_rstd[grp] * gnw[k];
        float bi = gnb[k] - g_mean[grp] * sc;
        float v  = xin[((size_t)(b * 64 + k) << 16) + pl + j];
        sX[k * 128 + j] = fmaxf(fmaf(v, sc, bi), 0.f);
    }
    if (t < 128) sR[t] = r[((size_t)b << 16) + pl + t];
    __syncthreads();

    int ty = t >> 4, tx = t & 15;
    float acc[8][8];
#pragma unroll
    for (int i = 0; i < 8; i++)
#pragma unroll
        for (int j = 0; j < 8; j++) acc[i][j] = 0.f;

#pragma unroll 8
    for (int k = 0; k < 64; k++) {
        const float* wr = sW + k * 128 + ty * 8;
        float4 a0 = *reinterpret_cast<const float4*>(wr);
        float4 a1 = *reinterpret_cast<const float4*>(wr + 4);
        const float* xr = sX + k * 128;
        float4 c0 = *reinterpret_cast<const float4*>(xr + tx * 4);
        float4 c1 = *reinterpret_cast<const float4*>(xr + 64 + tx * 4);
        float av[8] = {a0.x, a0.y, a0.z, a0.w, a1.x, a1.y, a1.z, a1.w};
        float bv[8] = {c0.x, c0.y, c0.z, c0.w, c1.x, c1.y, c1.z, c1.w};
#pragma unroll
        for (int i = 0; i < 8; i++)
#pragma unroll
            for (int j = 0; j < 8; j++)
                acc[i][j] = fmaf(av[i], bv[j], acc[i][j]);
    }

#pragma unroll
    for (int i = 0; i < 8; i++) {
        int m = ty * 8 + i;
        if (m < 64) {
            float* dst = g_U + (size_t)m * NPIX + p0;
            float4 v0 = make_float4(acc[i][0], acc[i][1], acc[i][2], acc[i][3]);
            float4 v1 = make_float4(acc[i][4], acc[i][5], acc[i][6], acc[i][7]);
            *reinterpret_cast<float4*>(dst + tx * 4) = v0;
            *reinterpret_cast<float4*>(dst + 64 + tx * 4) = v1;
        } else {
            int o = m - 64;
            float bb  = b1[o];
            float wp0 = w1[o * 131 + 128];
            float* dst = g_V + (size_t)o * NPIX + p0;
            float4 v0, v1;
            v0.x = acc[i][0] + bb - sR[tx * 4 + 0] * wp0;
            v0.y = acc[i][1] + bb - sR[tx * 4 + 1] * wp0;
            v0.z = acc[i][2] + bb - sR[tx * 4 + 2] * wp0;
            v0.w = acc[i][3] + bb - sR[tx * 4 + 3] * wp0;
            v1.x = acc[i][4] + bb - sR[64 + tx * 4 + 0] * wp0;
            v1.y = acc[i][5] + bb - sR[64 + tx * 4 + 1] * wp0;
            v1.z = acc[i][6] + bb - sR[64 + tx * 4 + 2] * wp0;
            v1.w = acc[i][7] + bb - sR[64 + tx * 4 + 3] * wp0;
            *reinterpret_cast<float4*>(dst + tx * 4) = v0;
            *reinterpret_cast<float4*>(dst + 64 + tx * 4) = v1;
        }
    }
}

// ---------------------------------------------------------------------------
// Edge-max: per 128-pixel tile loop 9 shifts, build t_s = relu(U_shift + V' +
// r_s*q_s) in smem, GEMM with w2 (64x64), running elementwise max, epilogue
// +b2 (+x residual if add_res). Shift wraps use &63 / &1023.
// ---------------------------------------------------------------------------
__global__ __launch_bounds__(256) void edge_max_kernel(
    const float* __restrict__ r, const float* __restrict__ w1,
    const float* __restrict__ w2, const float* __restrict__ b2,
    const float* __restrict__ xres, float* __restrict__ out, int add_res)
{
    extern __shared__ float sm[];
    float* sW2 = sm;             // 4096: [64][64] k-major
    float* sV  = sm + 4096;      // 8192
    float* sB  = sm + 12288;     // 8192
    float* sQ  = sm + 20480;     // 576: q vectors per shift
    float* sRs = sm + 21056;     // 128: shifted r
    float* sB2 = sm + 21184;     // 64

    int t  = threadIdx.x;
    int p0 = blockIdx.x << 7;
    int b  = p0 >> 16;
    int pl = p0 & 65535;
    int w0 = pl >> 10;
    int h0 = pl & 1023;

    for (int e = t; e < 4096; e += 256) {
        int o = e >> 6, k = e & 63;
        sW2[k * 64 + o] = w2[e];          // w2[o*64+k]
    }
    for (int e = t; e < 8192; e += 256) {
        int k = e >> 7, j = e & 127;
        sV[e] = g_V[((size_t)k << 18) + p0 + j];
    }
    for (int e = t; e < 576; e += 256) {
        int s = e >> 6, k = e & 63;
        int swv = s / 3 - 1, shv = s % 3 - 1;
        float ca = cosf(swv * AZI_C), sa = sinf(swv * AZI_C);
        float ci = cosf(shv * INC_C), si = sinf(shv * INC_C);
        sQ[e] = ca * ci * w1[k * 131 + 128] + ca * si * w1[k * 131 + 129]
              + sa * w1[k * 131 + 130];
    }
    if (t < 64) sB2[t] = b2[t];
    __syncthreads();

    int ty = t >> 4, tx = t & 15;
    float best[4][8];
#pragma unroll
    for (int i = 0; i < 4; i++)
#pragma unroll
        for (int j = 0; j < 8; j++) best[i][j] = -1e30f;

    for (int s = 0; s < 9; s++) {
        int swv = s / 3 - 1, shv = s % 3 - 1;
        int wsrc = (w0 - swv) & 63;
        size_t rowbase = ((size_t)b << 16) + ((size_t)wsrc << 10);
        if (t < 128) {
            int hs = (h0 + t - shv) & 1023;
            sRs[t] = r[rowbase + hs];
        }
        __syncthreads();
        for (int e = t; e < 8192; e += 256) {
            int k = e >> 7, j = e & 127;
            int hs = (h0 + j - shv) & 1023;
            float u = g_U[((size_t)k << 18) + rowbase + hs];
            sB[e] = fmaxf(fmaf(sRs[j], sQ[s * 64 + k], u + sV[e]), 0.f);
        }
        __syncthreads();

        float acc[4][8];
#pragma unroll
        for (int i = 0; i < 4; i++)
#pragma unroll
            for (int j = 0; j < 8; j++) acc[i][j] = 0.f;

#pragma unroll 8
        for (int k = 0; k < 64; k++) {
            float4 a  = *reinterpret_cast<const float4*>(sW2 + k * 64 + ty * 4);
            const float* br = sB + k * 128;
            float4 c0 = *reinterpret_cast<const float4*>(br + tx * 4);
            float4 c1 = *reinterpret_cast<const float4*>(br + 64 + tx * 4);
            float av[4] = {a.x, a.y, a.z, a.w};
            float bv[8] = {c0.x, c0.y, c0.z, c0.w, c1.x, c1.y, c1.z, c1.w};
#pragma unroll
            for (int i = 0; i < 4; i++)
#pragma unroll
                for (int j = 0; j < 8; j++)
                    acc[i][j] = fmaf(av[i], bv[j], acc[i][j]);
        }
#pragma unroll
        for (int i = 0; i < 4; i++)
#pragma unroll
            for (int j = 0; j < 8; j++)
                best[i][j] = fmaxf(best[i][j], acc[i][j]);
        __syncthreads();
    }

#pragma unroll
    for (int i = 0; i < 4; i++) {
        int o = ty * 4 + i;
        float bias = sB2[o];
        size_t obase = ((size_t)(b * 64 + o) << 16) + pl;
        float4 v0 = make_float4(best[i][0] + bias, best[i][1] + bias,
                                best[i][2] + bias, best[i][3] + bias);
        float4 v1 = make_float4(best[i][4] + bias, best[i][5] + bias,
                                best[i][6] + bias, best[i][7] + bias);
        if (add_res) {
            float4 x0 = *reinterpret_cast<const float4*>(xres + obase + tx * 4);
            float4 x1 = *reinterpret_cast<const float4*>(xres + obase + 64 + tx * 4);
            v0.x += x0.x; v0.y += x0.y; v0.z += x0.z; v0.w += x0.w;
            v1.x += x1.x; v1.y += x1.y; v1.z += x1.z; v1.w += x1.w;
        }
        *reinterpret_cast<float4*>(out + obase + tx * 4) = v0;
        *reinterpret_cast<float4*>(out + obase + 64 + tx * 4) = v1;
    }
}

// ---------------------------------------------------------------------------
extern "C" void kernel_launch(void* const* d_in, const int* in_sizes, int n_in,
                              void* d_out, int out_size) {
    const float* x     = (const float*)d_in[0];
    const float* r     = (const float*)d_in[1];
    const float* n1_w  = (const float*)d_in[2];
    const float* n1_b  = (const float*)d_in[3];
    const float* c1_w1 = (const float*)d_in[4];
    const float* c1_b1 = (const float*)d_in[5];
    const float* c1_w2 = (const float*)d_in[6];
    const float* c1_b2 = (const float*)d_in[7];
    const float* n2_w  = (const float*)d_in[8];
    const float* n2_b  = (const float*)d_in[9];
    const float* c2_w1 = (const float*)d_in[10];
    const float* c2_b1 = (const float*)d_in[11];
    const float* c2_w2 = (const float*)d_in[12];
    const float* c2_b2 = (const float*)d_in[13];
    float* out = (float*)d_out;

    const int GEMM_SMEM = 16512 * 4;   // 66048 B
    const int EDGE_SMEM = 21248 * 4;   // 84992 B
    cudaFuncSetAttribute(gemm_uv_kernel,
                         cudaFuncAttributeMaxDynamicSharedMemorySize, GEMM_SMEM);
    cudaFuncSetAttribute(edge_max_kernel,
                         cudaFuncAttributeMaxDynamicSharedMemorySize, EDGE_SMEM);

    // Block 1
    gn_stats_kernel<<<128, 256>>>(x);
    gemm_uv_kernel<<<2048, 256, GEMM_SMEM>>>(x, r, c1_w1, c1_b1, n1_w, n1_b);
    edge_max_kernel<<<2048, 256, EDGE_SMEM>>>(r, c1_w1, c1_w2, c1_b2,
                                              nullptr, out, 0);   // h1 -> d_out (scratch)
    // Block 2
    gn_stats_kernel<<<128, 256>>>(out);
    gemm_uv_kernel<<<2048, 256, GEMM_SMEM>>>(out, r, c2_w1, c2_b1, n2_w, n2_b);
    edge_max_kernel<<<2048, 256, EDGE_SMEM>>>(r, c2_w1, c2_w2, c2_b2,
                                              x, out, 1);         // out = x + h2
}

// round 4
// speedup vs baseline: 2.7193x; 2.7193x over previous
#include <cuda_runtime.h>
#include <cuda_bf16.h>
#include <cstdint>

#define NPIX 262144
#define AZI_C 0.006135923151542565f
#define INC_C 0.008267349088394194f

// scratch (device globals; no runtime alloc)
__device__ float g_UT[(size_t)NPIX * 64];   // pixel-major U  [pix][64]
__device__ float g_VT[(size_t)NPIX * 64];   // pixel-major V' [pix][64]
__device__ float g_mean[128], g_rstd[128];
__device__ float2 g_part[1024];

// ---------------- helpers ----------------
__device__ __forceinline__ uint32_t smem_u32(const void* p) {
    uint32_t a;
    asm("{ .reg .u64 t; cvta.to.shared.u64 t, %1; cvt.u32.u64 %0, t; }" : "=r"(a) : "l"(p));
    return a;
}
#define LDSM4(r0, r1, r2, r3, a) \
    asm volatile("ldmatrix.sync.aligned.m8n8.x4.shared.b16 {%0,%1,%2,%3}, [%4];" \
        : "=r"(r0), "=r"(r1), "=r"(r2), "=r"(r3) : "r"(a))
#define MMA(c0, c1, c2, c3, a0, a1, a2, a3, b0, b1) \
    asm volatile("mma.sync.aligned.m16n8k16.row.col.f32.bf16.bf16.f32 " \
        "{%0,%1,%2,%3},{%4,%5,%6,%7},{%8,%9},{%0,%1,%2,%3};" \
        : "+f"(c0), "+f"(c1), "+f"(c2), "+f"(c3) \
        : "r"(a0), "r"(a1), "r"(a2), "r"(a3), "r"(b0), "r"(b1))

__device__ __forceinline__ void split2(float a, float b, uint32_t& h, uint32_t& l) {
    __nv_bfloat162 hb = __floats2bfloat162_rn(a, b);
    float fa = __low2float(hb), fb = __high2float(hb);
    __nv_bfloat162 lb = __floats2bfloat162_rn(a - fa, b - fb);
    h = *reinterpret_cast<uint32_t*>(&hb);
    l = *reinterpret_cast<uint32_t*>(&lb);
}

// ---------------- GroupNorm stats, two-phase ----------------
__global__ void gn_part_kernel(const float* __restrict__ in) {
    int c = blockIdx.x, t = threadIdx.x;
    const float4* base = reinterpret_cast<const float4*>(in + (size_t)c * 16384);
    float s = 0.f, q = 0.f;
    for (int i = t; i < 4096; i += 256) {
        float4 v = base[i];
        s += (v.x + v.y) + (v.z + v.w);
        q += (v.x * v.x + v.y * v.y) + (v.z * v.z + v.w * v.w);
    }
    __shared__ float rs[256], rq[256];
    rs[t] = s; rq[t] = q;
    __syncthreads();
    for (int off = 128; off > 0; off >>= 1) {
        if (t < off) { rs[t] += rs[t + off]; rq[t] += rq[t + off]; }
        __syncthreads();
    }
    if (t == 0) g_part[c] = make_float2(rs[0], rq[0]);
}
__global__ void gn_fin_kernel() {
    int t = threadIdx.x;
    if (t < 128) {
        float s = 0.f, q = 0.f;
#pragma unroll
        for (int i = 0; i < 8; i++) { float2 p = g_part[t * 8 + i]; s += p.x; q += p.y; }
        float m = s * (1.f / 131072.f);
        g_mean[t] = m;
        g_rstd[t] = rsqrtf(q * (1.f / 131072.f) - m * m + 1e-6f);
    }
}

// ---------------- GEMM1: U,V' = relu(gn(x)) @ [Wa;Wb]^T via mma.sync ----------------
// smem: A hi [128][72]bf16, A lo, B hi [128][72]bf16, B lo, coefs
#define GA_H 0
#define GA_L 18432
#define GB_H 36864
#define GB_L 55296
#define G_CF 73728
#define G_SZ 74752

__global__ __launch_bounds__(256, 2) void gemm_mm_kernel(
    const float* __restrict__ xin, const float* __restrict__ r,
    const float* __restrict__ w1, const float* __restrict__ b1,
    const float* __restrict__ gnw, const float* __restrict__ gnb)
{
    extern __shared__ char smc[];
    uint32_t sb = smem_u32(smc);
    float* scf  = (float*)(smc + G_CF);
    float* bif  = scf + 64;
    float* b1f  = scf + 128;
    float* wp0f = scf + 192;

    int t = threadIdx.x, wid = t >> 5, ln = t & 31;
    int p0 = blockIdx.x << 7;
    int b = p0 >> 16, pl = p0 & 65535;

    if (t < 64) {
        int grp = (b << 5) + (t >> 1);
        float sc = g_rstd[grp] * gnw[t];
        scf[t]  = sc;
        bif[t]  = gnb[t] - g_mean[grp] * sc;
        b1f[t]  = b1[t];
        wp0f[t] = w1[t * 131 + 128];
    }
    // B = [Wa;Wb]: row n (output), col k. bf16 split, pitch 72.
    for (int e = t; e < 8192; e += 256) {
        int n = e >> 6, k = e & 63;
        float v = (n < 64) ? w1[n * 131 + k] : w1[(n - 64) * 131 + 64 + k];
        __nv_bfloat16 h = __float2bfloat16(v);
        __nv_bfloat16 l = __float2bfloat16(v - __bfloat162float(h));
        *(__nv_bfloat16*)(smc + GB_H + n * 144 + k * 2) = h;
        *(__nv_bfloat16*)(smc + GB_L + n * 144 + k * 2) = l;
    }
    // A = relu(gn(x)) pixel-major [128][64], bf16 split
    {
        int p = t & 127, co = (t >> 7) << 5;
        const float* xb = xin + (((size_t)(b * 64 + co)) << 16) + pl + p;
#pragma unroll
        for (int kc = 0; kc < 4; kc++) {
            float xv[8];
#pragma unroll
            for (int i = 0; i < 8; i++) {
                int k = co + kc * 8 + i;
                float raw = xb[((size_t)(kc * 8 + i)) << 16];
                xv[i] = fmaxf(fmaf(raw, scf[k], bif[k]), 0.f);
            }
            uint32_t h0, l0, h1, l1, h2, l2, h3, l3;
            split2(xv[0], xv[1], h0, l0);
            split2(xv[2], xv[3], h1, l1);
            split2(xv[4], xv[5], h2, l2);
            split2(xv[6], xv[7], h3, l3);
            uint32_t off = (uint32_t)(p * 144 + (co + kc * 8) * 2);
            *(uint4*)(smc + GA_H + off) = make_uint4(h0, h1, h2, h3);
            *(uint4*)(smc + GA_L + off) = make_uint4(l0, l1, l2, l3);
        }
    }
    __syncthreads();

    int wm = wid << 4;
    uint32_t aRow = sb + GA_H + (uint32_t)((wm + (ln & 15)) * 144 + ((ln >> 4) << 4));
    uint32_t bRow = sb + GB_H + (uint32_t)(((ln & 7)) * 144 + ((ln >> 3) << 4));

    float acc[16][4];
#pragma unroll
    for (int nb = 0; nb < 16; nb++)
#pragma unroll
        for (int j = 0; j < 4; j++) acc[nb][j] = 0.f;

#pragma unroll
    for (int kh = 0; kh < 2; kh++) {
        uint32_t ah[8], al[8];
        LDSM4(ah[0], ah[1], ah[2], ah[3], aRow + kh * 64);
        LDSM4(ah[4], ah[5], ah[6], ah[7], aRow + kh * 64 + 32);
        LDSM4(al[0], al[1], al[2], al[3], aRow + 18432 + kh * 64);
        LDSM4(al[4], al[5], al[6], al[7], aRow + 18432 + kh * 64 + 32);
#pragma unroll
        for (int nb = 0; nb < 16; nb++) {
            uint32_t bh[4], bl[4];
            uint32_t ba = bRow + (uint32_t)(nb * 1152 + kh * 64);
            LDSM4(bh[0], bh[1], bh[2], bh[3], ba);
            LDSM4(bl[0], bl[1], bl[2], bl[3], ba + 18432);
            MMA(acc[nb][0], acc[nb][1], acc[nb][2], acc[nb][3],
                ah[0], ah[1], ah[2], ah[3], bh[0], bh[1]);
            MMA(acc[nb][0], acc[nb][1], acc[nb][2], acc[nb][3],
                ah[4], ah[5], ah[6], ah[7], bh[2], bh[3]);
            MMA(acc[nb][0], acc[nb][1], acc[nb][2], acc[nb][3],
                ah[0], ah[1], ah[2], ah[3], bl[0], bl[1]);
            MMA(acc[nb][0], acc[nb][1], acc[nb][2], acc[nb][3],
                ah[4], ah[5], ah[6], ah[7], bl[2], bl[3]);
            MMA(acc[nb][0], acc[nb][1], acc[nb][2], acc[nb][3],
                al[0], al[1], al[2], al[3], bh[0], bh[1]);
            MMA(acc[nb][0], acc[nb][1], acc[nb][2], acc[nb][3],
                al[4], al[5], al[6], al[7], bh[2], bh[3]);
        }
    }

    // epilogue: thread holds pixels (wm + ln/4, +8), channels nb*8 + (ln%4)*2
    int pr0 = wm + (ln >> 2), pr1 = pr0 + 8;
    int cx = (ln & 3) << 1;
    size_t gp0 = (size_t)((b << 16) + pl + pr0);
    size_t gp1 = (size_t)((b << 16) + pl + pr1);
    float r0 = r[gp0], r1 = r[gp1];
#pragma unroll
    for (int nb = 0; nb < 16; nb++) {
        if (nb < 8) {
            int ch = nb * 8 + cx;
            *(float2*)(g_UT + gp0 * 64 + ch) = make_float2(acc[nb][0], acc[nb][1]);
            *(float2*)(g_UT + gp1 * 64 + ch) = make_float2(acc[nb][2], acc[nb][3]);
        } else {
            int ch = (nb - 8) * 8 + cx;
            float bb0 = b1f[ch], bb1 = b1f[ch + 1];
            float w0 = wp0f[ch], w1v = wp0f[ch + 1];
            *(float2*)(g_VT + gp0 * 64 + ch) =
                make_float2(acc[nb][0] + bb0 - r0 * w0, acc[nb][1] + bb1 - r0 * w1v);
            *(float2*)(g_VT + gp1 * 64 + ch) =
                make_float2(acc[nb][2] + bb0 - r1 * w0, acc[nb][3] + bb1 - r1 * w1v);
        }
    }
}

// ---------------- Edge-max via mma.sync ----------------
#define EA_H 0
#define EA_L 18432
#define EB_H 36864
#define EB_L 46080
#define E_V  55296
#define E_Q  90112
#define E_B2 92416
#define E_SZ 92672

__global__ __launch_bounds__(256, 2) void edge_mm_kernel(
    const float* __restrict__ r, const float* __restrict__ w1,
    const float* __restrict__ w2, const float* __restrict__ b2,
    const float* __restrict__ xres, float* __restrict__ out, int add_res)
{
    extern __shared__ char smc[];
    uint32_t sb = smem_u32(smc);
    float* sV  = (float*)(smc + E_V);    // [128][68]
    float* sQ  = (float*)(smc + E_Q);    // [9][64]
    float* sB2 = (float*)(smc + E_B2);   // [64]

    int t = threadIdx.x, wid = t >> 5, ln = t & 31;
    int p0 = blockIdx.x << 7;
    int b = p0 >> 16, pl = p0 & 65535;
    int w0 = pl >> 10, h0 = pl & 1023;

    // B = w2 [o][k] bf16 split, pitch 72
    for (int e = t; e < 4096; e += 256) {
        int o = e >> 6, k = e & 63;
        float v = w2[e];
        __nv_bfloat16 h = __float2bfloat16(v);
        __nv_bfloat16 l = __float2bfloat16(v - __bfloat162float(h));
        *(__nv_bfloat16*)(smc + EB_H + o * 144 + k * 2) = h;
        *(__nv_bfloat16*)(smc + EB_L + o * 144 + k * 2) = l;
    }
    int p = t & 127, co = (t >> 7) << 5;
    {   // V' tile into smem
        const float4* vb = reinterpret_cast<const float4*>(
            g_VT + ((size_t)((b << 16) + pl + p)) * 64 + co);
        float* d = sV + p * 68 + co;
#pragma unroll
        for (int i = 0; i < 8; i++) {
            float4 v = vb[i];
            d[i * 4 + 0] = v.x; d[i * 4 + 1] = v.y; d[i * 4 + 2] = v.z; d[i * 4 + 3] = v.w;
        }
    }
    for (int e = t; e < 576; e += 256) {
        int s = e >> 6, k = e & 63;
        int swv = s / 3 - 1, shv = s % 3 - 1;
        float ca = cosf(swv * AZI_C), sa = sinf(swv * AZI_C);
        float ci = cosf(shv * INC_C), si = sinf(shv * INC_C);
        sQ[e] = ca * ci * w1[k * 131 + 128] + ca * si * w1[k * 131 + 129]
              + sa * w1[k * 131 + 130];
    }
    if (t < 64) sB2[t] = b2[t];
    __syncthreads();

    int wm = wid << 4;
    uint32_t aRow = sb + EA_H + (uint32_t)((wm + (ln & 15)) * 144 + ((ln >> 4) << 4));
    uint32_t bRow = sb + EB_H + (uint32_t)(((ln & 7)) * 144 + ((ln >> 3) << 4));

    float best[8][4];
#pragma unroll
    for (int nb = 0; nb < 8; nb++)
#pragma unroll
        for (int j = 0; j < 4; j++) best[nb][j] = -1e30f;

    for (int s = 0; s < 9; s++) {
        int swv = s / 3 - 1, shv = s % 3 - 1;
        int wsrc = (w0 - swv) & 63;
        size_t rowb = ((size_t)(b << 16)) + ((size_t)wsrc << 10);
        // A build: t_s = relu(U_s + V' + r_s*q)
        {
            int hs = (h0 + p - shv) & 1023;
            const float* ub = g_UT + (rowb + hs) * 64 + co;
            float rs = __ldg(r + rowb + hs);
            const float* qv = sQ + s * 64 + co;
            const float* vv = sV + p * 68 + co;
#pragma unroll
            for (int kc = 0; kc < 4; kc++) {
                float4 u0 = *reinterpret_cast<const float4*>(ub + kc * 8);
                float4 u1 = *reinterpret_cast<const float4*>(ub + kc * 8 + 4);
                float uu[8] = {u0.x, u0.y, u0.z, u0.w, u1.x, u1.y, u1.z, u1.w};
                float xv[8];
#pragma unroll
                for (int i = 0; i < 8; i++) {
                    int k = kc * 8 + i;
                    xv[i] = fmaxf(fmaf(rs, qv[k], uu[i] + vv[k]), 0.f);
                }
                uint32_t h0r, l0r, h1r, l1r, h2r, l2r, h3r, l3r;
                split2(xv[0], xv[1], h0r, l0r);
                split2(xv[2], xv[3], h1r, l1r);
                split2(xv[4], xv[5], h2r, l2r);
                split2(xv[6], xv[7], h3r, l3r);
                uint32_t off = (uint32_t)(p * 144 + (co + kc * 8) * 2);
                *(uint4*)(smc + EA_H + off) = make_uint4(h0r, h1r, h2r, h3r);
                *(uint4*)(smc + EA_L + off) = make_uint4(l0r, l1r, l2r, l3r);
            }
        }
        __syncthreads();

        float acc[8][4];
#pragma unroll
        for (int nb = 0; nb < 8; nb++)
#pragma unroll
            for (int j = 0; j < 4; j++) acc[nb][j] = 0.f;

#pragma unroll
        for (int kh = 0; kh < 2; kh++) {
            uint32_t ah[8], al[8];
            LDSM4(ah[0], ah[1], ah[2], ah[3], aRow + kh * 64);
            LDSM4(ah[4], ah[5], ah[6], ah[7], aRow + kh * 64 + 32);
            LDSM4(al[0], al[1], al[2], al[3], aRow + 18432 + kh * 64);
            LDSM4(al[4], al[5], al[6], al[7], aRow + 18432 + kh * 64 + 32);
#pragma unroll
            for (int nb = 0; nb < 8; nb++) {
                uint32_t bh[4], bl[4];
                uint32_t ba = bRow + (uint32_t)(nb * 1152 + kh * 64);
                LDSM4(bh[0], bh[1], bh[2], bh[3], ba);
                LDSM4(bl[0], bl[1], bl[2], bl[3], ba + 9216);
                MMA(acc[nb][0], acc[nb][1], acc[nb][2], acc[nb][3],
                    ah[0], ah[1], ah[2], ah[3], bh[0], bh[1]);
                MMA(acc[nb][0], acc[nb][1], acc[nb][2], acc[nb][3],
                    ah[4], ah[5], ah[6], ah[7], bh[2], bh[3]);
                MMA(acc[nb][0], acc[nb][1], acc[nb][2], acc[nb][3],
                    ah[0], ah[1], ah[2], ah[3], bl[0], bl[1]);
                MMA(acc[nb][0], acc[nb][1], acc[nb][2], acc[nb][3],
                    ah[4], ah[5], ah[6], ah[7], bl[2], bl[3]);
                MMA(acc[nb][0], acc[nb][1], acc[nb][2], acc[nb][3],
                    al[0], al[1], al[2], al[3], bh[0], bh[1]);
                MMA(acc[nb][0], acc[nb][1], acc[nb][2], acc[nb][3],
                    al[4], al[5], al[6], al[7], bh[2], bh[3]);
            }
        }
#pragma unroll
        for (int nb = 0; nb < 8; nb++)
#pragma unroll
            for (int j = 0; j < 4; j++)
                best[nb][j] = fmaxf(best[nb][j], acc[nb][j]);
        __syncthreads();
    }

    // transpose through smem (reuse A region), then coalesced channel-major store
    float* sTr = (float*)(smc + EA_H);   // [128][66]
    {
        int pr0 = wm + (ln >> 2), pr1 = pr0 + 8;
        int cx = (ln & 3) << 1;
#pragma unroll
        for (int nb = 0; nb < 8; nb++) {
            int ch = nb * 8 + cx;
            *(float2*)(sTr + pr0 * 66 + ch) = make_float2(best[nb][0], best[nb][1]);
            *(float2*)(sTr + pr1 * 66 + ch) = make_float2(best[nb][2], best[nb][3]);
        }
    }
    __syncthreads();
#pragma unroll
    for (int i = 0; i < 32; i++) {
        int e = t + i * 256;
        int o = e >> 7, pix = e & 127;
        float v = sTr[pix * 66 + o] + sB2[o];
        size_t idx = (((size_t)(b * 64 + o)) << 16) + (pl + pix);
        if (add_res) v += xres[idx];
        out[idx] = v;
    }
}

// ---------------------------------------------------------------------------
extern "C" void kernel_launch(void* const* d_in, const int* in_sizes, int n_in,
                              void* d_out, int out_size) {
    const float* x     = (const float*)d_in[0];
    const float* r     = (const float*)d_in[1];
    const float* n1_w  = (const float*)d_in[2];
    const float* n1_b  = (const float*)d_in[3];
    const float* c1_w1 = (const float*)d_in[4];
    const float* c1_b1 = (const float*)d_in[5];
    const float* c1_w2 = (const float*)d_in[6];
    const float* c1_b2 = (const float*)d_in[7];
    const float* n2_w  = (const float*)d_in[8];
    const float* n2_b  = (const float*)d_in[9];
    const float* c2_w1 = (const float*)d_in[10];
    const float* c2_b1 = (const float*)d_in[11];
    const float* c2_w2 = (const float*)d_in[12];
    const float* c2_b2 = (const float*)d_in[13];
    float* out = (float*)d_out;

    cudaFuncSetAttribute(gemm_mm_kernel,
                         cudaFuncAttributeMaxDynamicSharedMemorySize, G_SZ);
    cudaFuncSetAttribute(edge_mm_kernel,
                         cudaFuncAttributeMaxDynamicSharedMemorySize, E_SZ);

    gn_part_kernel<<<1024, 256>>>(x);
    gn_fin_kernel<<<1, 128>>>();
    gemm_mm_kernel<<<2048, 256, G_SZ>>>(x, r, c1_w1, c1_b1, n1_w, n1_b);
    edge_mm_kernel<<<2048, 256, E_SZ>>>(r, c1_w1, c1_w2, c1_b2, nullptr, out, 0);

    gn_part_kernel<<<1024, 256>>>(out);
    gn_fin_kernel<<<1, 128>>>();
    gemm_mm_kernel<<<2048, 256, G_SZ>>>(out, r, c2_w1, c2_b1, n2_w, n2_b);
    edge_mm_kernel<<<2048, 256, E_SZ>>>(r, c2_w1, c2_w2, c2_b2, x, out, 1);
}